// round 5
// baseline (speedup 1.0000x reference)
#include <cuda_runtime.h>
#include <cstdint>
#include <cstddef>

// ---------------------------------------------------------------- constants
#define NB   4
#define NS_N 10000
#define NT_N 10000
#define NE   160000
#define NK   16
#define ND   128
#define M_NODES 40000
#define TILES_NODE 313
#define TILES_EDGE 5000
#define TILES_PER_BATCH 1250

// SMEM floats: A[2][128*132], B[128*136], partials 2*256
#define LDA 132
#define LDB 136
#define OFF_A1 (128 * LDA)             // 16896
#define OFF_B  (2 * OFF_A1)            // 33792
#define OFF_PS (OFF_B + 128 * LDB)     // 51200
#define OFF_PQ (OFF_PS + 256)          // 51456
#define SMEM_FLOATS (OFF_PQ + 256)     // 51712
#define SMEM_BYTES (SMEM_FLOATS * 4)   // 206848

#define GRID_P 148

// ---------------------------------------------------------------- scratch
__device__ float g_Ps[(size_t)NB * NS_N * ND];
__device__ float g_Pt[(size_t)NB * NT_N * ND];
__device__ float g_dbond[(size_t)NB * NE * ND];
__device__ float g_bred[(size_t)NB * NT_N * ND];
__device__ float g_tmp[(size_t)NB * NT_N * ND];

// ---------------------------------------------------------------- helpers
__device__ __forceinline__ unsigned f2tf(float f) {
    unsigned r; asm("cvt.rna.tf32.f32 %0, %1;" : "=r"(r) : "f"(f)); return r;
}
__device__ __forceinline__ void mma8(float c[4], const unsigned a[4], const unsigned b[2]) {
    asm volatile(
        "mma.sync.aligned.m16n8k8.row.col.f32.tf32.tf32.f32 "
        "{%0,%1,%2,%3},{%4,%5,%6,%7},{%8,%9},{%0,%1,%2,%3};"
        : "+f"(c[0]), "+f"(c[1]), "+f"(c[2]), "+f"(c[3])
        : "r"(a[0]), "r"(a[1]), "r"(a[2]), "r"(a[3]), "r"(b[0]), "r"(b[1]));
}
__device__ __forceinline__ float silu_f(float x) { return x / (1.f + __expf(-x)); }

__device__ __forceinline__ void prefetch_A(float* Adst, const float* __restrict__ Ag,
                                           size_t row0, size_t M, int tid) {
    uint32_t dst0 = (uint32_t)__cvta_generic_to_shared(Adst);
    #pragma unroll
    for (int i = 0; i < 16; ++i) {
        int t = tid + i * 256;
        int r = t >> 5, c4 = (t & 31) << 2;
        size_t rr = row0 + (size_t)r;
        if (rr >= M) rr = M - 1;
        uint32_t d = dst0 + (uint32_t)(r * LDA + c4) * 4u;
        const float* s = Ag + rr * ND + c4;
        asm volatile("cp.async.cg.shared.global [%0], [%1], 16;" :: "r"(d), "l"(s));
    }
}
__device__ __forceinline__ void cpa_commit() { asm volatile("cp.async.commit_group;" ::: "memory"); }
__device__ __forceinline__ void cpa_wait0()  { asm volatile("cp.async.wait_group 0;"  ::: "memory"); }

// weight stage: [k][n] row-major, tf32-rounded once
__device__ __forceinline__ void stage_W(float* Bsh, const float* __restrict__ W, int tid) {
    #pragma unroll
    for (int i = 0; i < 16; ++i) {
        int t = tid + i * 256;
        int r = t >> 5, c4 = (t & 31) << 2;
        float4 v = *(const float4*)(W + r * ND + c4);
        v.x = __uint_as_float(f2tf(v.x));
        v.y = __uint_as_float(f2tf(v.y));
        v.z = __uint_as_float(f2tf(v.z));
        v.w = __uint_as_float(f2tf(v.w));
        *(float4*)(Bsh + r * LDB + c4) = v;
    }
}

__device__ __forceinline__ void ldfragA(const float* Ash, int kk, int wm, int lr, int lc,
                                        unsigned a[8]) {
    int k0 = kk * 8;
    #pragma unroll
    for (int i = 0; i < 2; ++i) {
        int r = wm * 32 + i * 16 + lr;
        a[i * 4 + 0] = f2tf(Ash[r * LDA + k0 + lc]);
        a[i * 4 + 1] = f2tf(Ash[(r + 8) * LDA + k0 + lc]);
        a[i * 4 + 2] = f2tf(Ash[r * LDA + k0 + 4 + lc]);
        a[i * 4 + 3] = f2tf(Ash[(r + 8) * LDA + k0 + 4 + lc]);
    }
}
__device__ __forceinline__ void ldfragB(const float* Bsh, int kk, int wn, int lr, int lc,
                                        unsigned b[16]) {
    int k0 = kk * 8;
    #pragma unroll
    for (int j = 0; j < 8; ++j) {
        int n0 = wn * 64 + j * 8 + lr;
        b[j * 2 + 0] = __float_as_uint(Bsh[(k0 + lc) * LDB + n0]);
        b[j * 2 + 1] = __float_as_uint(Bsh[(k0 + 4 + lc) * LDB + n0]);
    }
}

// 128x128x128 tile GEMM: 8 warps (4 wm x 2 wn), warp tile 32x64, frag double-buffer
__device__ __forceinline__ void tile_gemm(const float* Ash, const float* Bsh,
                                          float c[2][8][4], int wm, int wn, int lr, int lc) {
    unsigned a0[8], a1[8], b0[16], b1[16];
    ldfragA(Ash, 0, wm, lr, lc, a0);
    ldfragB(Bsh, 0, wn, lr, lc, b0);
    #pragma unroll
    for (int kk = 0; kk < 16; ++kk) {
        unsigned* ac = (kk & 1) ? a1 : a0;
        unsigned* bc = (kk & 1) ? b1 : b0;
        unsigned* an = (kk & 1) ? a0 : a1;
        unsigned* bn = (kk & 1) ? b0 : b1;
        if (kk < 15) {
            ldfragA(Ash, kk + 1, wm, lr, lc, an);
            ldfragB(Bsh, kk + 1, wn, lr, lc, bn);
        }
        #pragma unroll
        for (int i = 0; i < 2; ++i)
            #pragma unroll
            for (int j = 0; j < 8; ++j)
                mma8(c[i][j], ac + i * 4, bc + j * 2);
    }
}

// ---------------------------------------------------------------- fused persistent GEMM
// MODE 0: out_main[gr] = acc                     (plain projection)
// MODE 1: edge — x=silu(acc+Ps[so]+Pt[to]); LN; g_dbond=y; out_main=bond+y
// MODE 2: tgt  — x=silu(acc+extra[gr]); LN; out_main = A(tgt) + y
template <int MODE>
__global__ __launch_bounds__(256) void gemm_fused(const float* __restrict__ Ag,
                                                  const float* __restrict__ Wg,
                                                  const float* __restrict__ extra,
                                                  const float* __restrict__ lng,
                                                  const float* __restrict__ lnb,
                                                  const int* __restrict__ so,
                                                  const int* __restrict__ to,
                                                  float* __restrict__ out_main,
                                                  int ntiles, size_t M) {
    extern __shared__ float sm[];
    float* Bsh = sm + OFF_B;
    int tid = threadIdx.x, lane = tid & 31, wid = tid >> 5;
    int wm = wid & 3, wn = wid >> 2;
    int lr = lane >> 2, lc = lane & 3;
    int colbase = wn * 64 + lc * 2;

    stage_W(Bsh, Wg, tid);

    float2 gg[8], bbv[8];
    if (MODE != 0) {
        #pragma unroll
        for (int j = 0; j < 8; ++j) {
            gg[j]  = *(const float2*)(lng + colbase + j * 8);
            bbv[j] = *(const float2*)(lnb + colbase + j * 8);
        }
    }

    if (blockIdx.x < (unsigned)ntiles)
        prefetch_A(sm, Ag, (size_t)blockIdx.x * 128, M, tid);
    cpa_commit();

    int buf = 0;
    for (int t = blockIdx.x; t < ntiles; t += gridDim.x, buf ^= 1) {
        cpa_wait0();
        __syncthreads();
        int tn = t + gridDim.x;
        if (tn < ntiles)
            prefetch_A(sm + (buf ^ 1) * OFF_A1, Ag, (size_t)tn * 128, M, tid);
        cpa_commit();

        const float* Ash = sm + buf * OFF_A1;
        float c[2][8][4];
        #pragma unroll
        for (int i = 0; i < 2; ++i)
            #pragma unroll
            for (int j = 0; j < 8; ++j) {
                c[i][j][0] = 0.f; c[i][j][1] = 0.f; c[i][j][2] = 0.f; c[i][j][3] = 0.f;
            }
        tile_gemm(Ash, Bsh, c, wm, wn, lr, lc);

        size_t row0 = (size_t)t * 128;

        if (MODE == 0) {
            #pragma unroll
            for (int i = 0; i < 2; ++i)
                #pragma unroll
                for (int h = 0; h < 2; ++h) {
                    int r = wm * 32 + i * 16 + lr + h * 8;
                    size_t gr = row0 + (size_t)r;
                    if (gr < M) {
                        float* o = out_main + gr * ND + colbase;
                        #pragma unroll
                        for (int j = 0; j < 8; ++j)
                            *(float2*)(o + j * 8) = make_float2(c[i][j][2 * h], c[i][j][2 * h + 1]);
                    }
                }
        } else {
            // -------- pass 1: activation + row partial sums --------
            int b = 0, el0 = 0;
            const float* PsB = nullptr;
            const float* PtB = nullptr;
            if (MODE == 1) {
                b = t / TILES_PER_BATCH;
                el0 = (t - b * TILES_PER_BATCH) * 128;
                PsB = g_Ps + (size_t)b * NS_N * ND;
                PtB = g_Pt + (size_t)b * NT_N * ND;
            }
            #pragma unroll
            for (int i = 0; i < 2; ++i)
                #pragma unroll
                for (int h = 0; h < 2; ++h) {
                    int r = wm * 32 + i * 16 + lr + h * 8;
                    float s = 0.f, q = 0.f;
                    if (MODE == 1) {
                        int el = el0 + r;
                        int si = __ldg(so + el);
                        int ti = __ldg(to + el);
                        const float* ps = PsB + (size_t)si * ND + colbase;
                        const float* pt = PtB + (size_t)ti * ND + colbase;
                        #pragma unroll
                        for (int j = 0; j < 8; ++j) {
                            float2 p = *(const float2*)(ps + j * 8);
                            float2 u = *(const float2*)(pt + j * 8);
                            float x0 = silu_f(c[i][j][2 * h]     + p.x + u.x);
                            float x1 = silu_f(c[i][j][2 * h + 1] + p.y + u.y);
                            c[i][j][2 * h] = x0; c[i][j][2 * h + 1] = x1;
                            s += x0 + x1; q += x0 * x0 + x1 * x1;
                        }
                    } else {
                        size_t gr = row0 + (size_t)r;
                        if (gr >= M) gr = M - 1;
                        const float* ex = extra + gr * ND + colbase;
                        #pragma unroll
                        for (int j = 0; j < 8; ++j) {
                            float2 p = *(const float2*)(ex + j * 8);
                            float x0 = silu_f(c[i][j][2 * h]     + p.x);
                            float x1 = silu_f(c[i][j][2 * h + 1] + p.y);
                            c[i][j][2 * h] = x0; c[i][j][2 * h + 1] = x1;
                            s += x0 + x1; q += x0 * x0 + x1 * x1;
                        }
                    }
                    s += __shfl_xor_sync(0xffffffffu, s, 1);
                    q += __shfl_xor_sync(0xffffffffu, q, 1);
                    s += __shfl_xor_sync(0xffffffffu, s, 2);
                    q += __shfl_xor_sync(0xffffffffu, q, 2);
                    if (lc == 0) {
                        sm[OFF_PS + wn * 128 + r] = s;
                        sm[OFF_PQ + wn * 128 + r] = q;
                    }
                }
            __syncthreads();
            // -------- pass 2: LN + residual + store --------
            #pragma unroll
            for (int i = 0; i < 2; ++i)
                #pragma unroll
                for (int h = 0; h < 2; ++h) {
                    int r = wm * 32 + i * 16 + lr + h * 8;
                    size_t gr = row0 + (size_t)r;
                    if (MODE == 2 && gr >= M) continue;
                    float s = sm[OFF_PS + r] + sm[OFF_PS + 128 + r];
                    float q = sm[OFF_PQ + r] + sm[OFF_PQ + 128 + r];
                    float mean = s * (1.f / ND);
                    float var  = q * (1.f / ND) - mean * mean;
                    float rstd = rsqrtf(var + 1e-5f);
                    size_t off = gr * ND + colbase;
                    const float* Arow = Ash + r * LDA + colbase;
                    #pragma unroll
                    for (int j = 0; j < 8; ++j) {
                        float y0 = (c[i][j][2 * h]     - mean) * rstd * gg[j].x + bbv[j].x;
                        float y1 = (c[i][j][2 * h + 1] - mean) * rstd * gg[j].y + bbv[j].y;
                        float2 av = *(const float2*)(Arow + j * 8);   // exact fp32 A (bond / tgt)
                        if (MODE == 1) {
                            *(float2*)(g_dbond + off + j * 8) = make_float2(y0, y1);
                            *(float2*)(out_main + off + j * 8) = make_float2(av.x + y0, av.y + y1);
                        } else {
                            *(float2*)(out_main + off + j * 8) = make_float2(av.x + y0, av.y + y1);
                        }
                    }
                }
        }
        __syncthreads();
    }
}

// ---------------------------------------------------------------- gather
__global__ __launch_bounds__(128) void gather_kernel(const int* __restrict__ edge_order,
                                                     const float* __restrict__ coef) {
    int bn = blockIdx.x;                 // 0 .. B*NT-1
    int b = bn / NT_N, nt = bn - b * NT_N;
    __shared__ int   eo[NK];
    __shared__ float cf[NK];
    if (threadIdx.x < NK) {
        eo[threadIdx.x] = edge_order[nt * NK + threadIdx.x];
        cf[threadIdx.x] = coef[nt * NK + threadIdx.x];
    }
    __syncthreads();
    int d = threadIdx.x;
    const float* base = g_dbond + (size_t)b * NE * ND;
    float acc = 0.f;
    #pragma unroll
    for (int k = 0; k < NK; ++k)
        acc += cf[k] * __ldg(base + (size_t)eo[k] * ND + d);
    g_bred[(size_t)bn * ND + d] = acc * (1.f / NK);
}

// ---------------------------------------------------------------- launch
extern "C" void kernel_launch(void* const* d_in, const int* in_sizes, int n_in,
                              void* d_out, int out_size) {
    const float* bond = (const float*)d_in[0];
    const float* src  = (const float*)d_in[1];
    const float* tgt  = (const float*)d_in[2];
    const float* Ws2e = (const float*)d_in[3];
    const float* Wt2e = (const float*)d_in[4];
    const float* We2e = (const float*)d_in[5];
    const float* ln1g = (const float*)d_in[6];
    const float* ln1b = (const float*)d_in[7];
    const float* We2t = (const float*)d_in[8];
    const float* Wt2t = (const float*)d_in[9];
    const float* ln2g = (const float*)d_in[10];
    const float* ln2b = (const float*)d_in[11];
    const float* coef = (const float*)d_in[12];
    const int* so = (const int*)d_in[13];
    const int* to = (const int*)d_in[14];
    const int* eo = (const int*)d_in[15];

    float* out0 = (float*)d_out;                     // [B,E,D]
    float* out1 = out0 + (size_t)NB * NE * ND;       // [B,NS,D]
    float* out2 = out1 + (size_t)NB * NS_N * ND;     // [B,NT,D]

    // device-symbol addresses for MODE0 outputs
    static float* s_Ps = nullptr;
    static float* s_Pt = nullptr;
    static float* s_bred = nullptr;
    static float* s_tmp = nullptr;
    if (!s_Ps) {
        cudaGetSymbolAddress((void**)&s_Ps, g_Ps);
        cudaGetSymbolAddress((void**)&s_Pt, g_Pt);
        cudaGetSymbolAddress((void**)&s_bred, g_bred);
        cudaGetSymbolAddress((void**)&s_tmp, g_tmp);
    }

    cudaFuncSetAttribute(gemm_fused<0>, cudaFuncAttributeMaxDynamicSharedMemorySize, SMEM_BYTES);
    cudaFuncSetAttribute(gemm_fused<1>, cudaFuncAttributeMaxDynamicSharedMemorySize, SMEM_BYTES);
    cudaFuncSetAttribute(gemm_fused<2>, cudaFuncAttributeMaxDynamicSharedMemorySize, SMEM_BYTES);

    // out1 = src
    cudaMemcpyAsync(out1, src, (size_t)NB * NS_N * ND * sizeof(float),
                    cudaMemcpyDeviceToDevice);

    // P_s = src @ W_s2e ; P_t = tgt @ W_t2e
    gemm_fused<0><<<GRID_P, 256, SMEM_BYTES>>>(src, Ws2e, nullptr, nullptr, nullptr,
                                               nullptr, nullptr, s_Ps, TILES_NODE, (size_t)M_NODES);
    gemm_fused<0><<<GRID_P, 256, SMEM_BYTES>>>(tgt, Wt2e, nullptr, nullptr, nullptr,
                                               nullptr, nullptr, s_Pt, TILES_NODE, (size_t)M_NODES);
    // edge block
    gemm_fused<1><<<GRID_P, 256, SMEM_BYTES>>>(bond, We2e, nullptr, ln1g, ln1b,
                                               so, to, out0, TILES_EDGE, (size_t)NB * NE);
    // bond -> node reduce
    gather_kernel<<<NB * NT_N, 128>>>(eo, coef);
    // g_tmp = bred @ We2t
    gemm_fused<0><<<GRID_P, 256, SMEM_BYTES>>>(s_bred, We2t, nullptr, nullptr, nullptr,
                                               nullptr, nullptr, s_tmp, TILES_NODE, (size_t)M_NODES);
    // out2 = tgt + LN(silu(tgt@Wt2t + g_tmp))
    gemm_fused<2><<<GRID_P, 256, SMEM_BYTES>>>(tgt, Wt2t, s_tmp, ln2g, ln2b,
                                               nullptr, nullptr, out2, TILES_NODE, (size_t)M_NODES);
}